// round 5
// baseline (speedup 1.0000x reference)
#include <cuda_runtime.h>
#include <math.h>

// Problem constants (fixed by setup_inputs)
#define NN   2000
#define EE   64000
#define EDD  16
#define ENHD 128
#define HH   64
#define TT   8
#define AHW  4096   // H*H

// ---------------- persistent device scratch (no allocs allowed) ----------------
__device__ short Aq_buf[(size_t)EE * AHW];      // 0.5 GB int16 A, [e][j][i]
__device__ float dq2_buf[EE * HH];              // per-(edge, j) dequant scale
__device__ float h1_buf[EE * ENHD];             // 32 MB
__device__ float W2p_buf[ENHD * AHW];           // permuted W2
__device__ float b2p_buf[AHW];
__device__ float xping[NN * HH];
__device__ float xpong[NN * HH];
__device__ float m_buf[NN * HH];

// ---------------- f32x2 packed-FMA helper (sm_103a) ----------------
__device__ __forceinline__ unsigned long long fma2(unsigned long long a,
                                                   unsigned long long b,
                                                   unsigned long long c) {
    unsigned long long d;
    asm("fma.rn.f32x2 %0, %1, %2, %3;" : "=l"(d) : "l"(a), "l"(b), "l"(c));
    return d;
}
__device__ __forceinline__ float2 u2f(unsigned long long u) {
    float2 v;
    asm("mov.b64 {%0, %1}, %2;" : "=f"(v.x), "=f"(v.y) : "l"(u));
    return v;
}

// ---------------- small utility kernels ----------------
__global__ void init_xm_kernel(const float* __restrict__ x_in) {
    int i = blockIdx.x * blockDim.x + threadIdx.x;
    if (i < NN * HH) { xping[i] = x_in[i]; m_buf[i] = 0.0f; }
}

__global__ void copy_out_kernel(float* __restrict__ out) {
    int i = blockIdx.x * blockDim.x + threadIdx.x;
    if (i < NN * HH) out[i] = xping[i];
}

// Permute W2 so the GEMM emits A in [e][j][i] layout:
//   W2p[k][j*64+i] = W2[k][i*64+j]
__global__ void permute_w2_kernel(const float* __restrict__ W2,
                                  const float* __restrict__ b2) {
    int idx = blockIdx.x * blockDim.x + threadIdx.x;
    if (idx >= ENHD * AHW) return;
    int k = idx / AHW;
    int c = idx % AHW;             // c = i*64 + j
    int i = c / HH, j = c % HH;
    W2p_buf[k * AHW + j * HH + i] = W2[idx];
    if (k == 0) b2p_buf[j * HH + i] = b2[c];
}

// ---------------- edge feature MLP layer 1: h1 = relu(ef @ W1 + b1) ----------------
__global__ void h1_kernel(const int* __restrict__ edges,
                          const float* __restrict__ edge_data,
                          const float* __restrict__ W1,
                          const float* __restrict__ b1) {
    __shared__ float ef[8][EDD];
    int t = threadIdx.x;
    int e0 = blockIdx.x * 8;

    {
        int el = t >> 4;
        int f  = t & 15;
        int e  = e0 + el;
        int src = edges[2 * e];
        int tgt = edges[2 * e + 1];
        ef[el][f] = edge_data[((size_t)src * NN + tgt) * EDD + f];
    }
    __syncthreads();

    int c = t;  // output column 0..127
    float acc[8];
#pragma unroll
    for (int el = 0; el < 8; el++) acc[el] = b1[c];
#pragma unroll
    for (int k = 0; k < EDD; k++) {
        float w = W1[k * ENHD + c];
#pragma unroll
        for (int el = 0; el < 8; el++) acc[el] += ef[el][k] * w;
    }
#pragma unroll
    for (int el = 0; el < 8; el++) {
        float v = acc[el];
        h1_buf[(size_t)(e0 + el) * ENHD + c] = v > 0.0f ? v : 0.0f;
    }
}

// ---------------- A-gen GEMM + fused int16 quantization ----------------
// A = relu(h1[64000x128] @ W2p[128x4096] + b2p), quantized per-(edge, j-block).
// BM=64 edges, BN=64 cols (one j), BK=16, 256 threads, 4x4 microtile.
// As2 holds pre-duplicated float2{v,v} so FFMA2 operands come straight from LDS.
__global__ void __launch_bounds__(256)
agen_kernel() {
    __shared__ __align__(16) float2 As2[16][66];   // [kk][m] duplicated pairs
    __shared__ __align__(16) float  Bs[16][68];    // [kk][n]

    int tid = threadIdx.x;
    int tx = tid & 15;   // n group
    int ty = tid >> 4;   // m group
    int e0 = blockIdx.y * 64;
    int n0 = blockIdx.x * 64;   // = j * 64, block covers one j for 64 edges

    unsigned long long acc[4][2];
#pragma unroll
    for (int i = 0; i < 4; i++) { acc[i][0] = 0ull; acc[i][1] = 0ull; }

    int lm  = tid >> 2;          // 0..63  row of A tile
    int lk4 = (tid & 3) * 4;     // 0,4,8,12
    int lkk = tid >> 4;          // 0..15  row of B tile
    int ln4 = (tid & 15) * 4;    // 0..60

    for (int k0 = 0; k0 < ENHD; k0 += 16) {
        {
            const float4 g = *reinterpret_cast<const float4*>(
                &h1_buf[(size_t)(e0 + lm) * ENHD + k0 + lk4]);
            As2[lk4 + 0][lm] = make_float2(g.x, g.x);
            As2[lk4 + 1][lm] = make_float2(g.y, g.y);
            As2[lk4 + 2][lm] = make_float2(g.z, g.z);
            As2[lk4 + 3][lm] = make_float2(g.w, g.w);
        }
        {
            const float4 g = *reinterpret_cast<const float4*>(
                &W2p_buf[(size_t)(k0 + lkk) * AHW + n0 + ln4]);
            *reinterpret_cast<float4*>(&Bs[lkk][ln4]) = g;
        }
        __syncthreads();

#pragma unroll
        for (int kk = 0; kk < 16; kk++) {
            // a-dups: (a0,a0,a1,a1) and (a2,a2,a3,a3) via LDS.128
            ulonglong2 au0 = *reinterpret_cast<const ulonglong2*>(&As2[kk][ty * 4]);
            ulonglong2 au1 = *reinterpret_cast<const ulonglong2*>(&As2[kk][ty * 4 + 2]);
            // b-pairs: (b0,b1) and (b2,b3) packed via LDS.128
            ulonglong2 bu  = *reinterpret_cast<const ulonglong2*>(&Bs[kk][tx * 4]);
            acc[0][0] = fma2(au0.x, bu.x, acc[0][0]);
            acc[0][1] = fma2(au0.x, bu.y, acc[0][1]);
            acc[1][0] = fma2(au0.y, bu.x, acc[1][0]);
            acc[1][1] = fma2(au0.y, bu.y, acc[1][1]);
            acc[2][0] = fma2(au1.x, bu.x, acc[2][0]);
            acc[2][1] = fma2(au1.x, bu.y, acc[2][1]);
            acc[3][0] = fma2(au1.y, bu.x, acc[3][0]);
            acc[3][1] = fma2(au1.y, bu.y, acc[3][1]);
        }
        __syncthreads();
    }

    // ---- epilogue: bias + relu, per-(e,j) amax, quantize, int16 store ----
    int n = n0 + tx * 4;
    float4 bb = *reinterpret_cast<const float4*>(&b2p_buf[n]);
    float4 vals[4];
    float lmax[4];
#pragma unroll
    for (int i = 0; i < 4; i++) {
        float2 c01 = u2f(acc[i][0]);
        float2 c23 = u2f(acc[i][1]);
        float4 v;
        v.x = fmaxf(c01.x + bb.x, 0.0f);
        v.y = fmaxf(c01.y + bb.y, 0.0f);
        v.z = fmaxf(c23.x + bb.z, 0.0f);
        v.w = fmaxf(c23.y + bb.w, 0.0f);
        vals[i] = v;
        lmax[i] = fmaxf(fmaxf(v.x, v.y), fmaxf(v.z, v.w));
    }
    // butterfly max over the 16 tx lanes (half-warp; tx = lane & 15)
#pragma unroll
    for (int off = 1; off < 16; off <<= 1) {
#pragma unroll
        for (int i = 0; i < 4; i++)
            lmax[i] = fmaxf(lmax[i], __shfl_xor_sync(0xFFFFFFFFu, lmax[i], off));
    }
    int jblk = n0 >> 6;
#pragma unroll
    for (int i = 0; i < 4; i++) {
        int e = e0 + ty * 4 + i;
        float amax = lmax[i];
        float inv = amax > 0.0f ? 32767.0f / amax : 0.0f;
        short4 q;
        q.x = (short)__float2int_rn(vals[i].x * inv);
        q.y = (short)__float2int_rn(vals[i].y * inv);
        q.z = (short)__float2int_rn(vals[i].z * inv);
        q.w = (short)__float2int_rn(vals[i].w * inv);
        *reinterpret_cast<short4*>(&Aq_buf[(size_t)e * AHW + n]) = q;
        if (tx == 0)
            dq2_buf[e * HH + jblk] = amax * (1.0f / 32767.0f);
    }
}

// ---------------- per-step message kernel ----------------
// warp per edge; Aq stored [e][j][i] int16; dequant folded into x_j broadcast.
__global__ void __launch_bounds__(256)
msg_kernel(const int* __restrict__ edges, int sel) {
    const float* __restrict__ x = sel ? xpong : xping;
    int wid  = threadIdx.x >> 5;
    int lane = threadIdx.x & 31;
    int e = blockIdx.x * 8 + wid;

    int src = edges[2 * e];
    int tgt = edges[2 * e + 1];

    const float* xs = x + src * HH;
    const float* dqs = dq2_buf + e * HH;
    float xa = xs[lane]      * dqs[lane];
    float xb = xs[lane + 32] * dqs[lane + 32];

    const short2* Ap = reinterpret_cast<const short2*>(Aq_buf + (size_t)e * AHW);
    float m0 = 0.0f, m1 = 0.0f;

#pragma unroll 8
    for (int j = 0; j < 32; j++) {
        float xj = __shfl_sync(0xFFFFFFFFu, xa, j);
        short2 a = Ap[j * 32 + lane];
        m0 += (float)a.x * xj;
        m1 += (float)a.y * xj;
    }
#pragma unroll 8
    for (int j = 0; j < 32; j++) {
        float xj = __shfl_sync(0xFFFFFFFFu, xb, j);
        short2 a = Ap[(j + 32) * 32 + lane];
        m0 += (float)a.x * xj;
        m1 += (float)a.y * xj;
    }

    atomicAdd(&m_buf[tgt * HH + 2 * lane], m0);
    atomicAdd(&m_buf[tgt * HH + 2 * lane + 1], m1);
    if (src != tgt) {
        atomicAdd(&m_buf[src * HH + 2 * lane], m0);
        atomicAdd(&m_buf[src * HH + 2 * lane + 1], m1);
    }
}

// ---------------- GRU update (re-zeroes m_buf for the next step) ----------------
__global__ void __launch_bounds__(256)
gru_kernel(const float* __restrict__ W_ih, const float* __restrict__ W_hh,
           const float* __restrict__ b_ih, const float* __restrict__ b_hh,
           int sel) {
    const float* __restrict__ xin = sel ? xpong : xping;
    float* __restrict__ xout      = sel ? xping : xpong;

    __shared__ float xsm[4][HH];
    __shared__ float msm[4][HH];

    int t = threadIdx.x;
    int ln = t >> 6;           // node within block
    int c  = t & 63;           // hidden index
    int node = blockIdx.x * 4 + ln;

    xsm[ln][c] = xin[node * HH + c];
    msm[ln][c] = m_buf[node * HH + c];
    m_buf[node * HH + c] = 0.0f;   // re-zero for next step's atomics
    __syncthreads();

    float ar = b_ih[c],      az = b_ih[HH + c],      an = b_ih[2 * HH + c];
    float hr = b_hh[c],      hz = b_hh[HH + c],      hn = b_hh[2 * HH + c];

#pragma unroll 8
    for (int k = 0; k < HH; k++) {
        float xv = xsm[ln][k];
        float mv = msm[ln][k];
        const float* wi_x = &W_ih[k * 192];
        const float* wi_m = &W_ih[(HH + k) * 192];
        const float* wh   = &W_hh[k * 192];
        ar += xv * wi_x[c]           + mv * wi_m[c];
        az += xv * wi_x[HH + c]      + mv * wi_m[HH + c];
        an += xv * wi_x[2 * HH + c]  + mv * wi_m[2 * HH + c];
        hr += xv * wh[c];
        hz += xv * wh[HH + c];
        hn += xv * wh[2 * HH + c];
    }

    float r = 1.0f / (1.0f + expf(-(ar + hr)));
    float z = 1.0f / (1.0f + expf(-(az + hz)));
    float n = tanhf(an + r * hn);
    xout[node * HH + c] = (1.0f - z) * n + z * xsm[ln][c];
}

// ---------------- launch ----------------
extern "C" void kernel_launch(void* const* d_in, const int* in_sizes, int n_in,
                              void* d_out, int out_size) {
    const float* x_in      = (const float*)d_in[0];
    // d_in[1] = adj (unused)
    const float* edge_data = (const float*)d_in[2];
    const int*   edges     = (const int*)  d_in[3];
    // d_in[4] = T (fixed = 8 by setup_inputs)
    const float* W1        = (const float*)d_in[5];
    const float* b1        = (const float*)d_in[6];
    const float* W2        = (const float*)d_in[7];
    const float* b2        = (const float*)d_in[8];
    const float* W_ih      = (const float*)d_in[9];
    const float* W_hh      = (const float*)d_in[10];
    const float* b_ih      = (const float*)d_in[11];
    const float* b_hh      = (const float*)d_in[12];
    float* out             = (float*)d_out;

    // precompute
    permute_w2_kernel<<<(ENHD * AHW + 255) / 256, 256>>>(W2, b2);
    h1_kernel<<<EE / 8, 128>>>(edges, edge_data, W1, b1);
    agen_kernel<<<dim3(AHW / 64, EE / 64), 256>>>();
    init_xm_kernel<<<(NN * HH + 255) / 256, 256>>>(x_in);

    for (int t = 0; t < TT; t++) {
        int sel = t & 1;
        msg_kernel<<<EE / 8, 256>>>(edges, sel);
        gru_kernel<<<NN / 4, 256>>>(W_ih, W_hh, b_ih, b_hh, sel);
    }
    // after 8 steps result is back in xping
    copy_out_kernel<<<(NN * HH + 255) / 256, 256>>>(out);
}

// round 6
// speedup vs baseline: 1.1867x; 1.1867x over previous
#include <cuda_runtime.h>
#include <math.h>

// Problem constants (fixed by setup_inputs)
#define NN   2000
#define EE   64000
#define EDD  16
#define ENHD 128
#define HH   64
#define TT   8
#define AHW  4096   // H*H

// ---------------- persistent device scratch (no allocs allowed) ----------------
__device__ short Aq_buf[(size_t)EE * AHW];      // 0.5 GB int16 A, [e][j][i]
__device__ float dq2_buf[EE * HH];              // per-(edge, j) dequant scale
__device__ float h1_buf[EE * ENHD];             // 32 MB
__device__ float W2p_buf[ENHD * AHW];           // permuted W2
__device__ float b2p_buf[AHW];
__device__ float xping[NN * HH];
__device__ float xpong[NN * HH];
__device__ float m_buf[NN * HH];

// ---------------- f32x2 packed-FMA helpers (sm_103a) ----------------
__device__ __forceinline__ unsigned long long f2u(float lo, float hi) {
    unsigned long long r;
    asm("mov.b64 %0, {%1, %2};" : "=l"(r) : "f"(lo), "f"(hi));
    return r;
}
__device__ __forceinline__ unsigned long long dup2(float v) {
    unsigned long long r;
    asm("mov.b64 %0, {%1, %1};" : "=l"(r) : "f"(v));
    return r;
}
__device__ __forceinline__ float2 u2f(unsigned long long u) {
    float2 v;
    asm("mov.b64 {%0, %1}, %2;" : "=f"(v.x), "=f"(v.y) : "l"(u));
    return v;
}
__device__ __forceinline__ unsigned long long fma2(unsigned long long a,
                                                   unsigned long long b,
                                                   unsigned long long c) {
    unsigned long long d;
    asm("fma.rn.f32x2 %0, %1, %2, %3;" : "=l"(d) : "l"(a), "l"(b), "l"(c));
    return d;
}

// ---------------- small utility kernels ----------------
__global__ void init_xm_kernel(const float* __restrict__ x_in) {
    int i = blockIdx.x * blockDim.x + threadIdx.x;
    if (i < NN * HH) { xping[i] = x_in[i]; m_buf[i] = 0.0f; }
}

__global__ void copy_out_kernel(float* __restrict__ out) {
    int i = blockIdx.x * blockDim.x + threadIdx.x;
    if (i < NN * HH) out[i] = xping[i];
}

// Permute W2 so the GEMM emits A in [e][j][i] layout:
//   W2p[k][j*64+i] = W2[k][i*64+j]
__global__ void permute_w2_kernel(const float* __restrict__ W2,
                                  const float* __restrict__ b2) {
    int idx = blockIdx.x * blockDim.x + threadIdx.x;
    if (idx >= ENHD * AHW) return;
    int k = idx / AHW;
    int c = idx % AHW;             // c = i*64 + j
    int i = c / HH, j = c % HH;
    W2p_buf[k * AHW + j * HH + i] = W2[idx];
    if (k == 0) b2p_buf[j * HH + i] = b2[c];
}

// ---------------- edge feature MLP layer 1: h1 = relu(ef @ W1 + b1) ----------------
__global__ void h1_kernel(const int* __restrict__ edges,
                          const float* __restrict__ edge_data,
                          const float* __restrict__ W1,
                          const float* __restrict__ b1) {
    __shared__ float ef[8][EDD];
    int t = threadIdx.x;
    int e0 = blockIdx.x * 8;

    {
        int el = t >> 4;
        int f  = t & 15;
        int e  = e0 + el;
        int src = edges[2 * e];
        int tgt = edges[2 * e + 1];
        ef[el][f] = edge_data[((size_t)src * NN + tgt) * EDD + f];
    }
    __syncthreads();

    int c = t;  // output column 0..127
    float acc[8];
#pragma unroll
    for (int el = 0; el < 8; el++) acc[el] = b1[c];
#pragma unroll
    for (int k = 0; k < EDD; k++) {
        float w = W1[k * ENHD + c];
#pragma unroll
        for (int el = 0; el < 8; el++) acc[el] += ef[el][k] * w;
    }
#pragma unroll
    for (int el = 0; el < 8; el++) {
        float v = acc[el];
        h1_buf[(size_t)(e0 + el) * ENHD + c] = v > 0.0f ? v : 0.0f;
    }
}

// ---------------- A-gen GEMM + fused int16 quantization ----------------
// A = relu(h1[64000x128] @ W2p[128x4096] + b2p), quantized per-(edge, j-block).
// BM=64 edges, BN=64 cols (one j), BK=16, 256 threads, 4x4 microtile.
// Inner loop is the R4-proven dup2/f2u schedule (measured fma=49.2%).
__global__ void __launch_bounds__(256)
agen_kernel() {
    __shared__ float As[16][68];   // [kk][m], padded
    __shared__ float Bs[16][68];   // [kk][n], padded

    int tid = threadIdx.x;
    int tx = tid & 15;   // n group
    int ty = tid >> 4;   // m group
    int e0 = blockIdx.y * 64;
    int n0 = blockIdx.x * 64;   // = j * 64, block covers one j for 64 edges

    unsigned long long acc[4][2];
#pragma unroll
    for (int i = 0; i < 4; i++) { acc[i][0] = 0ull; acc[i][1] = 0ull; }

    int lm  = tid >> 2;          // 0..63  row of A tile
    int lk4 = (tid & 3) * 4;     // 0,4,8,12
    int lkk = tid >> 4;          // 0..15  row of B tile
    int ln4 = (tid & 15) * 4;    // 0..60

    for (int k0 = 0; k0 < ENHD; k0 += 16) {
        {
            const float4 g = *reinterpret_cast<const float4*>(
                &h1_buf[(size_t)(e0 + lm) * ENHD + k0 + lk4]);
            As[lk4 + 0][lm] = g.x;
            As[lk4 + 1][lm] = g.y;
            As[lk4 + 2][lm] = g.z;
            As[lk4 + 3][lm] = g.w;
        }
        {
            const float4 g = *reinterpret_cast<const float4*>(
                &W2p_buf[(size_t)(k0 + lkk) * AHW + n0 + ln4]);
            *reinterpret_cast<float4*>(&Bs[lkk][ln4]) = g;
        }
        __syncthreads();

#pragma unroll
        for (int kk = 0; kk < 16; kk++) {
            float4 a4 = *reinterpret_cast<const float4*>(&As[kk][ty * 4]);
            float4 b4 = *reinterpret_cast<const float4*>(&Bs[kk][tx * 4]);
            unsigned long long b01 = f2u(b4.x, b4.y);
            unsigned long long b23 = f2u(b4.z, b4.w);
            unsigned long long a0 = dup2(a4.x);
            unsigned long long a1 = dup2(a4.y);
            unsigned long long a2 = dup2(a4.z);
            unsigned long long a3 = dup2(a4.w);
            acc[0][0] = fma2(a0, b01, acc[0][0]);
            acc[0][1] = fma2(a0, b23, acc[0][1]);
            acc[1][0] = fma2(a1, b01, acc[1][0]);
            acc[1][1] = fma2(a1, b23, acc[1][1]);
            acc[2][0] = fma2(a2, b01, acc[2][0]);
            acc[2][1] = fma2(a2, b23, acc[2][1]);
            acc[3][0] = fma2(a3, b01, acc[3][0]);
            acc[3][1] = fma2(a3, b23, acc[3][1]);
        }
        __syncthreads();
    }

    // ---- epilogue: bias + relu, per-(e,j) amax, quantize, int16 store ----
    int n = n0 + tx * 4;
    float4 bb = *reinterpret_cast<const float4*>(&b2p_buf[n]);
    float4 vals[4];
    float lmax[4];
#pragma unroll
    for (int i = 0; i < 4; i++) {
        float2 c01 = u2f(acc[i][0]);
        float2 c23 = u2f(acc[i][1]);
        float4 v;
        v.x = fmaxf(c01.x + bb.x, 0.0f);
        v.y = fmaxf(c01.y + bb.y, 0.0f);
        v.z = fmaxf(c23.x + bb.z, 0.0f);
        v.w = fmaxf(c23.y + bb.w, 0.0f);
        vals[i] = v;
        lmax[i] = fmaxf(fmaxf(v.x, v.y), fmaxf(v.z, v.w));
    }
    // butterfly max over the 16 tx lanes (tx = lane & 15)
#pragma unroll
    for (int off = 1; off < 16; off <<= 1) {
#pragma unroll
        for (int i = 0; i < 4; i++)
            lmax[i] = fmaxf(lmax[i], __shfl_xor_sync(0xFFFFFFFFu, lmax[i], off));
    }
    int jblk = n0 >> 6;
#pragma unroll
    for (int i = 0; i < 4; i++) {
        int e = e0 + ty * 4 + i;
        float amax = lmax[i];
        float inv = amax > 0.0f ? 32767.0f / amax : 0.0f;
        short4 q;
        q.x = (short)__float2int_rn(vals[i].x * inv);
        q.y = (short)__float2int_rn(vals[i].y * inv);
        q.z = (short)__float2int_rn(vals[i].z * inv);
        q.w = (short)__float2int_rn(vals[i].w * inv);
        *reinterpret_cast<short4*>(&Aq_buf[(size_t)e * AHW + n]) = q;
        if (tx == 0)
            dq2_buf[e * HH + jblk] = amax * (1.0f / 32767.0f);
    }
}

// ---------------- per-step message kernel ----------------
// warp per edge; Aq stored [e][j][i] int16; dequant folded into x_j broadcast.
__global__ void __launch_bounds__(256)
msg_kernel(const int* __restrict__ edges, int sel) {
    const float* __restrict__ x = sel ? xpong : xping;
    int wid  = threadIdx.x >> 5;
    int lane = threadIdx.x & 31;
    int e = blockIdx.x * 8 + wid;

    int src = edges[2 * e];
    int tgt = edges[2 * e + 1];

    const float* xs = x + src * HH;
    const float* dqs = dq2_buf + e * HH;
    float xa = xs[lane]      * dqs[lane];
    float xb = xs[lane + 32] * dqs[lane + 32];

    const short2* Ap = reinterpret_cast<const short2*>(Aq_buf + (size_t)e * AHW);
    float m0 = 0.0f, m1 = 0.0f;

#pragma unroll 8
    for (int j = 0; j < 32; j++) {
        float xj = __shfl_sync(0xFFFFFFFFu, xa, j);
        short2 a = Ap[j * 32 + lane];
        m0 += (float)a.x * xj;
        m1 += (float)a.y * xj;
    }
#pragma unroll 8
    for (int j = 0; j < 32; j++) {
        float xj = __shfl_sync(0xFFFFFFFFu, xb, j);
        short2 a = Ap[(j + 32) * 32 + lane];
        m0 += (float)a.x * xj;
        m1 += (float)a.y * xj;
    }

    atomicAdd(&m_buf[tgt * HH + 2 * lane], m0);
    atomicAdd(&m_buf[tgt * HH + 2 * lane + 1], m1);
    if (src != tgt) {
        atomicAdd(&m_buf[src * HH + 2 * lane], m0);
        atomicAdd(&m_buf[src * HH + 2 * lane + 1], m1);
    }
}

// ---------------- GRU update (re-zeroes m_buf for the next step) ----------------
__global__ void __launch_bounds__(256)
gru_kernel(const float* __restrict__ W_ih, const float* __restrict__ W_hh,
           const float* __restrict__ b_ih, const float* __restrict__ b_hh,
           int sel) {
    const float* __restrict__ xin = sel ? xpong : xping;
    float* __restrict__ xout      = sel ? xping : xpong;

    __shared__ float xsm[4][HH];
    __shared__ float msm[4][HH];

    int t = threadIdx.x;
    int ln = t >> 6;           // node within block
    int c  = t & 63;           // hidden index
    int node = blockIdx.x * 4 + ln;

    xsm[ln][c] = xin[node * HH + c];
    msm[ln][c] = m_buf[node * HH + c];
    m_buf[node * HH + c] = 0.0f;   // re-zero for next step's atomics
    __syncthreads();

    float ar = b_ih[c],      az = b_ih[HH + c],      an = b_ih[2 * HH + c];
    float hr = b_hh[c],      hz = b_hh[HH + c],      hn = b_hh[2 * HH + c];

#pragma unroll 8
    for (int k = 0; k < HH; k++) {
        float xv = xsm[ln][k];
        float mv = msm[ln][k];
        const float* wi_x = &W_ih[k * 192];
        const float* wi_m = &W_ih[(HH + k) * 192];
        const float* wh   = &W_hh[k * 192];
        ar += xv * wi_x[c]           + mv * wi_m[c];
        az += xv * wi_x[HH + c]      + mv * wi_m[HH + c];
        an += xv * wi_x[2 * HH + c]  + mv * wi_m[2 * HH + c];
        hr += xv * wh[c];
        hz += xv * wh[HH + c];
        hn += xv * wh[2 * HH + c];
    }

    float r = 1.0f / (1.0f + expf(-(ar + hr)));
    float z = 1.0f / (1.0f + expf(-(az + hz)));
    float n = tanhf(an + r * hn);
    xout[node * HH + c] = (1.0f - z) * n + z * xsm[ln][c];
}

// ---------------- launch ----------------
extern "C" void kernel_launch(void* const* d_in, const int* in_sizes, int n_in,
                              void* d_out, int out_size) {
    const float* x_in      = (const float*)d_in[0];
    // d_in[1] = adj (unused)
    const float* edge_data = (const float*)d_in[2];
    const int*   edges     = (const int*)  d_in[3];
    // d_in[4] = T (fixed = 8 by setup_inputs)
    const float* W1        = (const float*)d_in[5];
    const float* b1        = (const float*)d_in[6];
    const float* W2        = (const float*)d_in[7];
    const float* b2        = (const float*)d_in[8];
    const float* W_ih      = (const float*)d_in[9];
    const float* W_hh      = (const float*)d_in[10];
    const float* b_ih      = (const float*)d_in[11];
    const float* b_hh      = (const float*)d_in[12];
    float* out             = (float*)d_out;

    // precompute (init first so ncu's fixed sample slot lands on agen)
    init_xm_kernel<<<(NN * HH + 255) / 256, 256>>>(x_in);
    permute_w2_kernel<<<(ENHD * AHW + 255) / 256, 256>>>(W2, b2);
    h1_kernel<<<EE / 8, 128>>>(edges, edge_data, W1, b1);
    agen_kernel<<<dim3(AHW / 64, EE / 64), 256>>>();

    for (int t = 0; t < TT; t++) {
        int sel = t & 1;
        msg_kernel<<<EE / 8, 256>>>(edges, sel);
        gru_kernel<<<NN / 4, 256>>>(W_ih, W_hh, b_ih, b_hh, sel);
    }
    // after 8 steps result is back in xping
    copy_out_kernel<<<(NN * HH + 255) / 256, 256>>>(out);
}

// round 7
// speedup vs baseline: 1.4270x; 1.2025x over previous
#include <cuda_runtime.h>
#include <math.h>

// Problem constants (fixed by setup_inputs)
#define NN   2000
#define EE   64000
#define EDD  16
#define ENHD 128
#define HH   64
#define TT   8
#define AHW  4096   // H*H

// ---------------- persistent device scratch (no allocs allowed) ----------------
__device__ short Aq_buf[(size_t)EE * AHW];      // 0.5 GB int16 A, [e][j][i]
__device__ float dq2_buf[EE * HH];              // per-(edge, j) dequant scale
__device__ float h1_buf[EE * ENHD];             // 32 MB
__device__ float W2p_buf[ENHD * AHW];           // permuted W2
__device__ float b2p_buf[AHW];
__device__ float xping[NN * HH];
__device__ float xpong[NN * HH];
__device__ float m_buf[NN * HH];

// ---------------- f32x2 packed-FMA helpers (sm_103a) ----------------
__device__ __forceinline__ unsigned long long dup2(float v) {
    unsigned long long r;
    asm("mov.b64 %0, {%1, %1};" : "=l"(r) : "f"(v));
    return r;
}
__device__ __forceinline__ float2 u2f(unsigned long long u) {
    float2 v;
    asm("mov.b64 {%0, %1}, %2;" : "=f"(v.x), "=f"(v.y) : "l"(u));
    return v;
}
__device__ __forceinline__ unsigned long long fma2(unsigned long long a,
                                                   unsigned long long b,
                                                   unsigned long long c) {
    unsigned long long d;
    asm("fma.rn.f32x2 %0, %1, %2, %3;" : "=l"(d) : "l"(a), "l"(b), "l"(c));
    return d;
}

// ---------------- small utility kernels ----------------
__global__ void init_xm_kernel(const float* __restrict__ x_in) {
    int i = blockIdx.x * blockDim.x + threadIdx.x;
    if (i < NN * HH) { xping[i] = x_in[i]; m_buf[i] = 0.0f; }
}

__global__ void copy_out_kernel(float* __restrict__ out) {
    int i = blockIdx.x * blockDim.x + threadIdx.x;
    if (i < NN * HH) out[i] = xping[i];
}

// Permute W2 so the GEMM emits A in [e][j][i] layout:
//   W2p[k][j*64+i] = W2[k][i*64+j]
__global__ void permute_w2_kernel(const float* __restrict__ W2,
                                  const float* __restrict__ b2) {
    int idx = blockIdx.x * blockDim.x + threadIdx.x;
    if (idx >= ENHD * AHW) return;
    int k = idx / AHW;
    int c = idx % AHW;             // c = i*64 + j
    int i = c / HH, j = c % HH;
    W2p_buf[k * AHW + j * HH + i] = W2[idx];
    if (k == 0) b2p_buf[j * HH + i] = b2[c];
}

// ---------------- edge feature MLP layer 1: h1 = relu(ef @ W1 + b1) ----------------
__global__ void h1_kernel(const int* __restrict__ edges,
                          const float* __restrict__ edge_data,
                          const float* __restrict__ W1,
                          const float* __restrict__ b1) {
    __shared__ float ef[8][EDD];
    int t = threadIdx.x;
    int e0 = blockIdx.x * 8;

    {
        int el = t >> 4;
        int f  = t & 15;
        int e  = e0 + el;
        int src = edges[2 * e];
        int tgt = edges[2 * e + 1];
        ef[el][f] = edge_data[((size_t)src * NN + tgt) * EDD + f];
    }
    __syncthreads();

    int c = t;  // output column 0..127
    float acc[8];
#pragma unroll
    for (int el = 0; el < 8; el++) acc[el] = b1[c];
#pragma unroll
    for (int k = 0; k < EDD; k++) {
        float w = W1[k * ENHD + c];
#pragma unroll
        for (int el = 0; el < 8; el++) acc[el] += ef[el][k] * w;
    }
#pragma unroll
    for (int el = 0; el < 8; el++) {
        float v = acc[el];
        h1_buf[(size_t)(e0 + el) * ENHD + c] = v > 0.0f ? v : 0.0f;
    }
}

__device__ __forceinline__ int pack2s(float a, float b, float inv) {
    int lo = __float2int_rn(a * inv);
    int hi = __float2int_rn(b * inv);
    return (lo & 0xFFFF) | (hi << 16);
}

// ---------------- A-gen GEMM + fused int16 quantization ----------------
// A = relu(h1[64000x128] @ W2p[128x4096] + b2p), quantized per-(edge, j-block).
// BM=128 edges, BN=128 cols (2 j-blocks), BK=16, 256 threads, 8x8 microtile.
// A-read: 16-lane broadcast (conflict-free). B-read: float4 at 16B stride
// (conflict-free). Doubles FLOP per LDS byte vs the 4x4 tile (L1 was 97%).
__global__ void __launch_bounds__(256, 2)
agen_kernel() {
    __shared__ float  As[16][132];        // [kk][m], padded
    __shared__ float4 Bs4[16][2][16];     // [kk][half][tx] = cols tx*8+4h..+3

    int tid = threadIdx.x;
    int tx = tid & 15;   // n group: cols n0 + tx*8 .. +7
    int ty = tid >> 4;   // m group: rows e0 + ty*8 .. +7
    int e0 = blockIdx.y * 128;
    int n0 = blockIdx.x * 128;

    unsigned long long acc[8][4];
#pragma unroll
    for (int r = 0; r < 8; r++)
#pragma unroll
        for (int p = 0; p < 4; p++) acc[r][p] = 0ull;

    int lm  = tid >> 1;          // 0..127 row of A tile
    int lk8 = (tid & 1) * 8;     // 0 or 8
    int lkk = tid >> 4;          // 0..15 row of B tile
    int tb  = tid & 15;          // B col group

    for (int k0 = 0; k0 < ENHD; k0 += 16) {
        // As fill: 2 float4 per thread, transposed to [kk][m]
        {
            const float* src = &h1_buf[(size_t)(e0 + lm) * ENHD + k0 + lk8];
            float4 g0 = *reinterpret_cast<const float4*>(src);
            float4 g1 = *reinterpret_cast<const float4*>(src + 4);
            As[lk8 + 0][lm] = g0.x;
            As[lk8 + 1][lm] = g0.y;
            As[lk8 + 2][lm] = g0.z;
            As[lk8 + 3][lm] = g0.w;
            As[lk8 + 4][lm] = g1.x;
            As[lk8 + 5][lm] = g1.y;
            As[lk8 + 6][lm] = g1.z;
            As[lk8 + 7][lm] = g1.w;
        }
        // Bs fill: direct STS.128, layout already matches the read pattern
        {
            const float* src = &W2p_buf[(size_t)(k0 + lkk) * AHW + n0 + tb * 8];
            Bs4[lkk][0][tb] = *reinterpret_cast<const float4*>(src);
            Bs4[lkk][1][tb] = *reinterpret_cast<const float4*>(src + 4);
        }
        __syncthreads();

#pragma unroll
        for (int kk = 0; kk < 16; kk++) {
            float4 alo = *reinterpret_cast<const float4*>(&As[kk][ty * 8]);
            float4 ahi = *reinterpret_cast<const float4*>(&As[kk][ty * 8 + 4]);
            ulonglong2 bu0 = *reinterpret_cast<const ulonglong2*>(&Bs4[kk][0][tx]);
            ulonglong2 bu1 = *reinterpret_cast<const ulonglong2*>(&Bs4[kk][1][tx]);
            float av[8] = {alo.x, alo.y, alo.z, alo.w, ahi.x, ahi.y, ahi.z, ahi.w};
#pragma unroll
            for (int r = 0; r < 8; r++) {
                unsigned long long ad = dup2(av[r]);
                acc[r][0] = fma2(ad, bu0.x, acc[r][0]);
                acc[r][1] = fma2(ad, bu0.y, acc[r][1]);
                acc[r][2] = fma2(ad, bu1.x, acc[r][2]);
                acc[r][3] = fma2(ad, bu1.y, acc[r][3]);
            }
        }
        __syncthreads();
    }

    // ---- epilogue: bias + relu, per-(e, j-block) amax, quantize, int16 store ----
    int nb = n0 + tx * 8;
    float4 bb0 = *reinterpret_cast<const float4*>(&b2p_buf[nb]);
    float4 bb1 = *reinterpret_cast<const float4*>(&b2p_buf[nb + 4]);

    float vals[8][8];
    float lmax[8];
#pragma unroll
    for (int r = 0; r < 8; r++) {
        float2 c0 = u2f(acc[r][0]);
        float2 c1 = u2f(acc[r][1]);
        float2 c2 = u2f(acc[r][2]);
        float2 c3 = u2f(acc[r][3]);
        vals[r][0] = fmaxf(c0.x + bb0.x, 0.0f);
        vals[r][1] = fmaxf(c0.y + bb0.y, 0.0f);
        vals[r][2] = fmaxf(c1.x + bb0.z, 0.0f);
        vals[r][3] = fmaxf(c1.y + bb0.w, 0.0f);
        vals[r][4] = fmaxf(c2.x + bb1.x, 0.0f);
        vals[r][5] = fmaxf(c2.y + bb1.y, 0.0f);
        vals[r][6] = fmaxf(c3.x + bb1.z, 0.0f);
        vals[r][7] = fmaxf(c3.y + bb1.w, 0.0f);
        float m01 = fmaxf(fmaxf(vals[r][0], vals[r][1]), fmaxf(vals[r][2], vals[r][3]));
        float m23 = fmaxf(fmaxf(vals[r][4], vals[r][5]), fmaxf(vals[r][6], vals[r][7]));
        lmax[r] = fmaxf(m01, m23);
    }
    // butterfly max over the 8-lane tx subgroup (tx 0-7 = j-block 0, 8-15 = j-block 1)
#pragma unroll
    for (int off = 1; off < 8; off <<= 1) {
#pragma unroll
        for (int r = 0; r < 8; r++)
            lmax[r] = fmaxf(lmax[r], __shfl_xor_sync(0xFFFFFFFFu, lmax[r], off));
    }
    int jblk = (n0 >> 6) + (tx >> 3);   // this thread's j-block
#pragma unroll
    for (int r = 0; r < 8; r++) {
        int e = e0 + ty * 8 + r;
        float amax = lmax[r];
        float inv = amax > 0.0f ? 32767.0f / amax : 0.0f;
        int4 q;
        q.x = pack2s(vals[r][0], vals[r][1], inv);
        q.y = pack2s(vals[r][2], vals[r][3], inv);
        q.z = pack2s(vals[r][4], vals[r][5], inv);
        q.w = pack2s(vals[r][6], vals[r][7], inv);
        *reinterpret_cast<int4*>(&Aq_buf[(size_t)e * AHW + nb]) = q;
        if ((tx & 7) == 0)
            dq2_buf[e * HH + jblk] = amax * (1.0f / 32767.0f);
    }
}

// ---------------- per-step message kernel ----------------
// warp per edge; Aq stored [e][j][i] int16; dequant folded into x_j broadcast.
__global__ void __launch_bounds__(256)
msg_kernel(const int* __restrict__ edges, int sel) {
    const float* __restrict__ x = sel ? xpong : xping;
    int wid  = threadIdx.x >> 5;
    int lane = threadIdx.x & 31;
    int e = blockIdx.x * 8 + wid;

    int src = edges[2 * e];
    int tgt = edges[2 * e + 1];

    const float* xs = x + src * HH;
    const float* dqs = dq2_buf + e * HH;
    float xa = xs[lane]      * dqs[lane];
    float xb = xs[lane + 32] * dqs[lane + 32];

    const short2* Ap = reinterpret_cast<const short2*>(Aq_buf + (size_t)e * AHW);
    float m0 = 0.0f, m1 = 0.0f;

#pragma unroll 8
    for (int j = 0; j < 32; j++) {
        float xj = __shfl_sync(0xFFFFFFFFu, xa, j);
        short2 a = Ap[j * 32 + lane];
        m0 += (float)a.x * xj;
        m1 += (float)a.y * xj;
    }
#pragma unroll 8
    for (int j = 0; j < 32; j++) {
        float xj = __shfl_sync(0xFFFFFFFFu, xb, j);
        short2 a = Ap[(j + 32) * 32 + lane];
        m0 += (float)a.x * xj;
        m1 += (float)a.y * xj;
    }

    atomicAdd(&m_buf[tgt * HH + 2 * lane], m0);
    atomicAdd(&m_buf[tgt * HH + 2 * lane + 1], m1);
    if (src != tgt) {
        atomicAdd(&m_buf[src * HH + 2 * lane], m0);
        atomicAdd(&m_buf[src * HH + 2 * lane + 1], m1);
    }
}

// ---------------- GRU update (re-zeroes m_buf for the next step) ----------------
__global__ void __launch_bounds__(256)
gru_kernel(const float* __restrict__ W_ih, const float* __restrict__ W_hh,
           const float* __restrict__ b_ih, const float* __restrict__ b_hh,
           int sel) {
    const float* __restrict__ xin = sel ? xpong : xping;
    float* __restrict__ xout      = sel ? xping : xpong;

    __shared__ float xsm[4][HH];
    __shared__ float msm[4][HH];

    int t = threadIdx.x;
    int ln = t >> 6;           // node within block
    int c  = t & 63;           // hidden index
    int node = blockIdx.x * 4 + ln;

    xsm[ln][c] = xin[node * HH + c];
    msm[ln][c] = m_buf[node * HH + c];
    m_buf[node * HH + c] = 0.0f;   // re-zero for next step's atomics
    __syncthreads();

    float ar = b_ih[c],      az = b_ih[HH + c],      an = b_ih[2 * HH + c];
    float hr = b_hh[c],      hz = b_hh[HH + c],      hn = b_hh[2 * HH + c];

#pragma unroll 8
    for (int k = 0; k < HH; k++) {
        float xv = xsm[ln][k];
        float mv = msm[ln][k];
        const float* wi_x = &W_ih[k * 192];
        const float* wi_m = &W_ih[(HH + k) * 192];
        const float* wh   = &W_hh[k * 192];
        ar += xv * wi_x[c]           + mv * wi_m[c];
        az += xv * wi_x[HH + c]      + mv * wi_m[HH + c];
        an += xv * wi_x[2 * HH + c]  + mv * wi_m[2 * HH + c];
        hr += xv * wh[c];
        hz += xv * wh[HH + c];
        hn += xv * wh[2 * HH + c];
    }

    float r = 1.0f / (1.0f + expf(-(ar + hr)));
    float z = 1.0f / (1.0f + expf(-(az + hz)));
    float n = tanhf(an + r * hn);
    xout[node * HH + c] = (1.0f - z) * n + z * xsm[ln][c];
}

// ---------------- launch ----------------
extern "C" void kernel_launch(void* const* d_in, const int* in_sizes, int n_in,
                              void* d_out, int out_size) {
    const float* x_in      = (const float*)d_in[0];
    // d_in[1] = adj (unused)
    const float* edge_data = (const float*)d_in[2];
    const int*   edges     = (const int*)  d_in[3];
    // d_in[4] = T (fixed = 8 by setup_inputs)
    const float* W1        = (const float*)d_in[5];
    const float* b1        = (const float*)d_in[6];
    const float* W2        = (const float*)d_in[7];
    const float* b2        = (const float*)d_in[8];
    const float* W_ih      = (const float*)d_in[9];
    const float* W_hh      = (const float*)d_in[10];
    const float* b_ih      = (const float*)d_in[11];
    const float* b_hh      = (const float*)d_in[12];
    float* out             = (float*)d_out;

    // precompute (init first so ncu's fixed sample slot lands on agen)
    init_xm_kernel<<<(NN * HH + 255) / 256, 256>>>(x_in);
    permute_w2_kernel<<<(ENHD * AHW + 255) / 256, 256>>>(W2, b2);
    h1_kernel<<<EE / 8, 128>>>(edges, edge_data, W1, b1);
    agen_kernel<<<dim3(AHW / 128, EE / 128), 256>>>();

    for (int t = 0; t < TT; t++) {
        int sel = t & 1;
        msg_kernel<<<EE / 8, 256>>>(edges, sel);
        gru_kernel<<<NN / 4, 256>>>(W_ih, W_hh, b_ih, b_hh, sel);
    }
    // after 8 steps result is back in xping
    copy_out_kernel<<<(NN * HH + 255) / 256, 256>>>(out);
}